// round 2
// baseline (speedup 1.0000x reference)
#include <cuda_runtime.h>

// ZNCC: per-channel 5x5 local normalized cross-correlation, then mean over C.
// x,y: [B=16, C=3, H=512, W=512] f32.  out: [B,1,H,W] f32.
//
// Per-pixel math (zero-padded 5x5 box means, /25 everywhere):
//   mx = box(x); my = box(y); xc = x-mx; yc = y-my
//   ncc = box(xc*yc) / (sqrt(box(xc*xc))*sqrt(box(yc*yc)) + 1e-8)
//   out = mean_c(ncc)
// NOTE: the second box filter zero-pads the PRODUCTS outside the image —
// products at out-of-image positions must be forced to 0.
//
// Fused single kernel: 32x32 output tile per CTA, 9x9 effective stencil
// (halo 4). Two rounds of separable 5-tap box sums in shared memory.

#define BATCH 16
#define CHAN  3
#define HH    512
#define WW    512

#define TILE 32
#define HALO 4
#define INSZ 40   // TILE + 2*HALO
#define MIDS 36   // TILE + 4  (region where means/products are needed)

// padded strides (odd -> conflict-free column walks)
#define INP 41
#define HP  37
#define PP  37
#define QP  33

#define SMEM_FLOATS (2*INSZ*INP + 2*INSZ*HP + 3*MIDS*PP + 3*MIDS*QP)

__global__ __launch_bounds__(256, 4)
void zncc_fused_kernel(const float* __restrict__ x,
                       const float* __restrict__ y,
                       float* __restrict__ out)
{
    extern __shared__ float smem[];
    float* sx  = smem;                 // [INSZ][INP]
    float* sy  = sx  + INSZ*INP;       // [INSZ][INP]
    float* hx  = sy  + INSZ*INP;       // [INSZ][HP]   horizontal 5-sum of x
    float* hy  = hx  + INSZ*HP;        // [INSZ][HP]
    float* pxy = hy  + INSZ*HP;        // [MIDS][PP]   centered products
    float* pxx = pxy + MIDS*PP;
    float* pyy = pxx + MIDS*PP;
    float* qxy = pyy + MIDS*PP;        // [MIDS][QP]   horizontal 5-sum of products
    float* qxx = qxy + MIDS*QP;
    float* qyy = qxx + MIDS*QP;

    const int tx  = threadIdx.x;           // 0..31
    const int ty  = threadIdx.y;           // 0..7
    const int tid = ty * 32 + tx;
    const int tileX = blockIdx.x * TILE;
    const int tileY = blockIdx.y * TILE;
    const int b = blockIdx.z;

    const float inv25 = 1.0f / 25.0f;

    float acc0 = 0.f, acc1 = 0.f, acc2 = 0.f, acc3 = 0.f;

    for (int ch = 0; ch < CHAN; ch++) {
        const float* xb = x + ((size_t)(b * CHAN + ch)) * (HH * WW);
        const float* yb = y + ((size_t)(b * CHAN + ch)) * (HH * WW);

        // ---- load 40x40 halo tile of x and y (zero pad outside image) ----
        #pragma unroll
        for (int idx = tid; idx < INSZ * INSZ; idx += 256) {
            int r = idx / INSZ;
            int c = idx - r * INSZ;
            int gy = tileY - HALO + r;
            int gx = tileX - HALO + c;
            bool ok = (gy >= 0) & (gy < HH) & (gx >= 0) & (gx < WW);
            size_t g = (size_t)gy * WW + gx;
            sx[r * INP + c] = ok ? __ldg(xb + g) : 0.0f;
            sy[r * INP + c] = ok ? __ldg(yb + g) : 0.0f;
        }
        __syncthreads();

        // ---- horizontal 5-sum pass 1: 40 rows x 36 cols ----
        for (int idx = tid; idx < INSZ * MIDS; idx += 256) {
            int r = idx / MIDS;
            int c = idx - r * MIDS;
            const float* p = &sx[r * INP + c];
            hx[r * HP + c] = p[0] + p[1] + p[2] + p[3] + p[4];
            const float* q = &sy[r * INP + c];
            hy[r * HP + c] = q[0] + q[1] + q[2] + q[3] + q[4];
        }
        __syncthreads();

        // ---- vertical 5-sum pass 1 -> means; centered products: 36x36 ----
        // Products must be ZERO outside the image (second reduce_window
        // zero-pads the product maps).
        for (int idx = tid; idx < MIDS * MIDS; idx += 256) {
            int r = idx / MIDS;
            int c = idx - r * MIDS;
            const float* p = &hx[r * HP + c];
            float mx = (p[0] + p[HP] + p[2*HP] + p[3*HP] + p[4*HP]) * inv25;
            const float* q = &hy[r * HP + c];
            float my = (q[0] + q[HP] + q[2*HP] + q[3*HP] + q[4*HP]) * inv25;
            float xc = sx[(r + 2) * INP + (c + 2)] - mx;
            float yc = sy[(r + 2) * INP + (c + 2)] - my;
            int gr = tileY - 2 + r;
            int gc = tileX - 2 + c;
            bool in = (gr >= 0) & (gr < HH) & (gc >= 0) & (gc < WW);
            if (!in) { xc = 0.0f; yc = 0.0f; }
            pxy[r * PP + c] = xc * yc;
            pxx[r * PP + c] = xc * xc;
            pyy[r * PP + c] = yc * yc;
        }
        __syncthreads();

        // ---- horizontal 5-sum pass 2: 36 rows x 32 cols ----
        for (int idx = tid; idx < MIDS * TILE; idx += 256) {
            int r = idx >> 5;           // / 32
            int c = idx & 31;
            const float* a = &pxy[r * PP + c];
            qxy[r * QP + c] = a[0] + a[1] + a[2] + a[3] + a[4];
            const float* bb = &pxx[r * PP + c];
            qxx[r * QP + c] = bb[0] + bb[1] + bb[2] + bb[3] + bb[4];
            const float* cc = &pyy[r * PP + c];
            qyy[r * QP + c] = cc[0] + cc[1] + cc[2] + cc[3] + cc[4];
        }
        __syncthreads();

        // ---- vertical 5-sum pass 2 + NCC: each thread does 4 output rows ----
        {
            float* accp[4] = {&acc0, &acc1, &acc2, &acc3};
            #pragma unroll
            for (int k = 0; k < 4; k++) {
                int r = ty + 8 * k;     // output row within tile -> q rows r..r+4
                const float* a = &qxy[r * QP + tx];
                float axy = (a[0] + a[QP] + a[2*QP] + a[3*QP] + a[4*QP]) * inv25;
                const float* bb = &qxx[r * QP + tx];
                float axx = (bb[0] + bb[QP] + bb[2*QP] + bb[3*QP] + bb[4*QP]) * inv25;
                const float* cc = &qyy[r * QP + tx];
                float ayy = (cc[0] + cc[QP] + cc[2*QP] + cc[3*QP] + cc[4*QP]) * inv25;
                *accp[k] += axy / (sqrtf(axx) * sqrtf(ayy) + 1e-8f);
            }
        }
        __syncthreads();   // before buffers are reused by next channel
    }

    // ---- write channel-mean ----
    const float inv3 = 1.0f / 3.0f;
    {
        int gx = tileX + tx;
        size_t base = ((size_t)b * HH) * WW + gx;
        out[base + (size_t)(tileY + ty +  0) * WW] = acc0 * inv3;
        out[base + (size_t)(tileY + ty +  8) * WW] = acc1 * inv3;
        out[base + (size_t)(tileY + ty + 16) * WW] = acc2 * inv3;
        out[base + (size_t)(tileY + ty + 24) * WW] = acc3 * inv3;
    }
}

extern "C" void kernel_launch(void* const* d_in, const int* in_sizes, int n_in,
                              void* d_out, int out_size)
{
    const float* x = (const float*)d_in[0];
    const float* y = (const float*)d_in[1];
    float* out = (float*)d_out;

    const int smem_bytes = SMEM_FLOATS * sizeof(float);   // ~55 KB
    cudaFuncSetAttribute(zncc_fused_kernel,
                         cudaFuncAttributeMaxDynamicSharedMemorySize,
                         smem_bytes);

    dim3 block(32, 8, 1);
    dim3 grid(WW / TILE, HH / TILE, BATCH);   // 16 x 16 x 16
    zncc_fused_kernel<<<grid, block, smem_bytes>>>(x, y, out);
}